// round 15
// baseline (speedup 1.0000x reference)
#include <cuda_runtime.h>
#include <cstddef>

// ---------------------------------------------------------------------------
// Persistent kernel, 64x256 tiles, 512-thread blocks (16 warps: latency
// hiding), M-paired fma.rn.f32x2 inner loop (A pairs free via swizzled
// float4 reads, only B duplicated), conflict-free XOR-swizzled A smem,
// register-prefetched staging, splitK=8 consumer-side summation,
// Wvoih0 + Whw1 GEMM fusions.  Schedule identical to R14.
// ---------------------------------------------------------------------------

#define NBLK 148
#define NTHR 512

namespace {
constexpr int HID = 1024;
constexpr int LAT = 256;
constexpr int BSZ = 64;
constexpr int H3  = 3 * HID;
constexpr size_t GI_STR  = (size_t)BSZ * H3;    // 196608
constexpr size_t GIN_STR = (size_t)BSZ * HID;   // 65536
constexpr size_t NZ_STR  = (size_t)BSZ * LAT;   // 16384
}

// -------------------- device scratch ---------------------------------------
__device__ __align__(16) float S_Wvo   [HID * HID];
__device__ __align__(16) float S_Wvoih0[(size_t)HID * H3];
__device__ __align__(16) float S_Whw1  [HID * HID];
__device__ __align__(16) float S_bvo   [HID];
__device__ __align__(16) float S_bvoih0[H3];
__device__ __align__(16) float S_bhw1b1[HID];
__device__ __align__(16) float S_gi [8 * BSZ * H3];
__device__ __align__(16) float S_gh0[8 * BSZ * H3];
__device__ __align__(16) float S_gh1[8 * BSZ * H3];
__device__ __align__(16) float S_gin[8 * BSZ * HID];
__device__ __align__(16) float S_X1 [8 * BSZ * HID];
__device__ __align__(16) float S_nz [8 * BSZ * LAT];
__device__ __align__(16) float S_h1 [BSZ * HID];
__device__ __align__(16) float S_h2 [BSZ * HID];

// -------------------- device-wide barrier (replay-invariant) ----------------
__device__ unsigned g_count = 0;
__device__ volatile unsigned g_gen = 0;

__device__ __forceinline__ void gsync() {
    __syncthreads();
    if (threadIdx.x == 0) {
        __threadfence();
        unsigned gen = g_gen;
        if (atomicAdd(&g_count, 1u) == NBLK - 1) {
            atomicExch(&g_count, 0u);
            __threadfence();
            g_gen = gen + 1;
        } else {
            while (g_gen == gen) { __nanosleep(32); }
        }
        __threadfence();
    }
    __syncthreads();
}

// -------------------- packed fp32x2 helpers --------------------------------
__device__ __forceinline__ float2 f2fma(float2 a, float2 b, float2 c) {
    unsigned long long ra = *reinterpret_cast<unsigned long long*>(&a);
    unsigned long long rb = *reinterpret_cast<unsigned long long*>(&b);
    unsigned long long rc = *reinterpret_cast<unsigned long long*>(&c);
    unsigned long long rd;
    asm("fma.rn.f32x2 %0, %1, %2, %3;" : "=l"(rd) : "l"(ra), "l"(rb), "l"(rc));
    return *reinterpret_cast<float2*>(&rd);
}
__device__ __forceinline__ float2 dup2(float a) {
    unsigned long long u;
    asm("mov.b64 %0, {%1, %1};" : "=l"(u) : "r"(__float_as_uint(a)));
    return *reinterpret_cast<float2*>(&u);
}
__device__ __forceinline__ float4 add4(float4 a, float4 b) {
    return make_float4(a.x + b.x, a.y + b.y, a.z + b.z, a.w + b.w);
}

// -------------------- shared memory ----------------------------------------
struct Smem {
    float As[32][64];     // [k][m ^ ((k>>2)<<2)]  8 KB, conflict-free
    float Bs[32][260];    // [k][n]                33.3 KB
    float red[NTHR];
};

// ---------------------------------------------------------------------------
// One 64x256 tile: C = act(sum_{p<NACC} A_p)[64,Klen] @ W[Klen,256] (+bias).
// 512 threads: (tc 0..63, tr 0..7) -> rows tr*8..+7 (4 f32x2 row-pairs),
// cols tc*4..+3.  A row-pairs come directly from swizzled float4 reads.
// ---------------------------------------------------------------------------
template<int NACC, bool RELU>
__device__ __noinline__ void gemm_tile(
    Smem* sm, const float* A, size_t astr, int lda, int Klen,
    const float* W, int ldw, const float* bias, float* C, int ldc)
{
    const int tid = threadIdx.x;
    const int tc = tid & 63, tr = tid >> 6;
    const int ml = tr * 8, nl = tc * 4;
    const int am = tid >> 3;             // A staging row 0..63 (1 slot/thread)
    const int kq = tid & 7;              // A staging k-group
    const int bkr0 = tid >> 6;           // B staging k-row base (i adds 8)
    const int bc4  = (tid & 63) * 4;     // B staging col

    float2 acc[4][4];
    #pragma unroll
    for (int p = 0; p < 4; p++)
        #pragma unroll
        for (int j = 0; j < 4; j++) acc[p][j] = make_float2(0.f, 0.f);

    float4 pa, pb[4];
    pa = *(const float4*)&A[(size_t)am * lda + kq * 4];
    #pragma unroll
    for (int i = 0; i < 4; i++)
        pb[i] = *(const float4*)&W[(size_t)(bkr0 + i * 8) * ldw + bc4];

    for (int k0 = 0; k0 < Klen; k0 += 32) {
        __syncthreads();                       // readers done with smem
        // ---- store staged A (sum partials, opt relu), XOR-swizzled col
        {
            float4 v = pa;
            if (NACC > 1) {
                const float* ap = A + (size_t)am * lda + k0 + kq * 4;
                #pragma unroll
                for (int pp = 1; pp < NACC; pp++)
                    v = add4(v, *(const float4*)(ap + (size_t)pp * astr));
            }
            if (RELU) {
                v.x = fmaxf(v.x, 0.f); v.y = fmaxf(v.y, 0.f);
                v.z = fmaxf(v.z, 0.f); v.w = fmaxf(v.w, 0.f);
            }
            const int col = am ^ (kq << 2);
            sm->As[kq * 4 + 0][col] = v.x;
            sm->As[kq * 4 + 1][col] = v.y;
            sm->As[kq * 4 + 2][col] = v.z;
            sm->As[kq * 4 + 3][col] = v.w;
        }
        // ---- store staged B
        #pragma unroll
        for (int i = 0; i < 4; i++)
            *(float4*)&sm->Bs[bkr0 + i * 8][bc4] = pb[i];
        // ---- prefetch next k-tile
        if (k0 + 32 < Klen) {
            const int kn = k0 + 32;
            pa = *(const float4*)&A[(size_t)am * lda + kn + kq * 4];
            #pragma unroll
            for (int i = 0; i < 4; i++)
                pb[i] = *(const float4*)&W[(size_t)(kn + bkr0 + i * 8) * ldw + bc4];
        }
        __syncthreads();                       // staged data visible

        #pragma unroll 8
        for (int kk = 0; kk < 32; kk++) {
            const int c0 = ml ^ ((kk >> 2) << 2);
            float4 a0 = *(const float4*)&sm->As[kk][c0];       // rows ml..+3
            float4 a1 = *(const float4*)&sm->As[kk][c0 ^ 4];   // rows ml+4..+7
            const float2* ap0 = (const float2*)&a0;            // pairs 0,1
            const float2* ap1 = (const float2*)&a1;            // pairs 2,3
            float4 b4 = *(const float4*)&sm->Bs[kk][nl];
            float2 bd[4] = { dup2(b4.x), dup2(b4.y), dup2(b4.z), dup2(b4.w) };
            #pragma unroll
            for (int j = 0; j < 4; j++) {
                acc[0][j] = f2fma(ap0[0], bd[j], acc[0][j]);
                acc[1][j] = f2fma(ap0[1], bd[j], acc[1][j]);
                acc[2][j] = f2fma(ap1[0], bd[j], acc[2][j]);
                acc[3][j] = f2fma(ap1[1], bd[j], acc[3][j]);
            }
        }
    }

    float4 bb = make_float4(0.f, 0.f, 0.f, 0.f);
    if (bias) bb = *(const float4*)&bias[nl];
    #pragma unroll
    for (int p = 0; p < 4; p++) {
        float4 v0 = make_float4(acc[p][0].x + bb.x, acc[p][1].x + bb.y,
                                acc[p][2].x + bb.z, acc[p][3].x + bb.w);
        float4 v1 = make_float4(acc[p][0].y + bb.x, acc[p][1].y + bb.y,
                                acc[p][2].y + bb.z, acc[p][3].y + bb.w);
        *(float4*)&C[(size_t)(ml + 2 * p)     * ldc + nl] = v0;
        *(float4*)&C[(size_t)(ml + 2 * p + 1) * ldc + nl] = v1;
    }
}

// split-K work item j: tile = j>>lg2s (n0 = tile*256), slice = j&mask
template<int NACC, bool RELU>
__device__ __forceinline__ void do_item(
    Smem* sm, int j, int lg2s, int Ktot,
    const float* A, size_t astr, int lda,
    const float* W, int ldw, const float* bias,
    float* Cb, size_t cstr, int ldc)
{
    const int kh = j & ((1 << lg2s) - 1);
    const int n0 = (j >> lg2s) * 256;
    const int Klen = Ktot >> lg2s;
    const int ko = kh * Klen;
    gemm_tile<NACC, RELU>(sm, A + ko, astr, lda, Klen,
                          W + (size_t)ko * ldw + n0, ldw,
                          kh ? nullptr : (bias + n0),
                          Cb + kh * cstr + n0, ldc);
}

// -------------------- GRU elementwise (sums 8 partials) ---------------------
__device__ void gru_stage(const float* giB, const float* ghB, float* h)
{
    const float4* gi4 = (const float4*)giB;
    const float4* gh4 = (const float4*)ghB;
    float4* h4 = (float4*)h;
    const size_t bstr = GI_STR / 4;
    for (int i = blockIdx.x * NTHR + threadIdx.x; i < BSZ * HID / 4;
         i += NBLK * NTHR) {
        int m = i >> 8, c = i & 255;
        size_t g = (size_t)m * 768 + c;
        float4 ir = make_float4(0,0,0,0), iz = ir, in_ = ir;
        float4 hr = ir, hz = ir, hn = ir;
        #pragma unroll
        for (int p = 0; p < 8; p++) {
            size_t o = p * bstr + g;
            ir  = add4(ir,  gi4[o]);
            iz  = add4(iz,  gi4[o + 256]);
            in_ = add4(in_, gi4[o + 512]);
            hr  = add4(hr,  gh4[o]);
            hz  = add4(hz,  gh4[o + 256]);
            hn  = add4(hn,  gh4[o + 512]);
        }
        float4 hv = h4[i], res;
        res.x = [&]{ float r=1.f/(1.f+expf(-(ir.x+hr.x)));
                     float zz=1.f/(1.f+expf(-(iz.x+hz.x)));
                     float nn=tanhf(in_.x+r*hn.x);
                     return (1.f-zz)*nn+zz*hv.x; }();
        res.y = [&]{ float r=1.f/(1.f+expf(-(ir.y+hr.y)));
                     float zz=1.f/(1.f+expf(-(iz.y+hz.y)));
                     float nn=tanhf(in_.y+r*hn.y);
                     return (1.f-zz)*nn+zz*hv.y; }();
        res.z = [&]{ float r=1.f/(1.f+expf(-(ir.z+hr.z)));
                     float zz=1.f/(1.f+expf(-(iz.z+hz.z)));
                     float nn=tanhf(in_.z+r*hn.z);
                     return (1.f-zz)*nn+zz*hv.z; }();
        res.w = [&]{ float r=1.f/(1.f+expf(-(ir.w+hr.w)));
                     float zz=1.f/(1.f+expf(-(iz.w+hz.w)));
                     float nn=tanhf(in_.w+r*hn.w);
                     return (1.f-zz)*nn+zz*hv.w; }();
        h4[i] = res;
    }
}

// vector @ matrix: dst[n0+lane] = sum_k v[k]*M[k,n] (+addv).  512 threads.
__device__ void vecmatK(Smem* sm, const float* v, const float* M, int ldm,
                        int K, const float* addv, float* dst, int n0)
{
    const int tid = threadIdx.x;
    int nl = tid & 31, ks = tid >> 5;            // 16 k-slices
    const int seg = K >> 4;
    const float* col = M + n0 + nl;
    float s = 0.f;
    for (int k = ks * seg; k < ks * seg + seg; k++)
        s += v[k] * col[(size_t)k * ldm];
    sm->red[tid] = s;
    __syncthreads();
    if (tid < 32) {
        float t = addv ? addv[n0 + nl] : 0.f;
        #pragma unroll
        for (int q = 0; q < 16; q++) t += sm->red[nl + 32 * q];
        dst[n0 + nl] = t;
    }
    __syncthreads();
}

// ---------------------------------------------------------------------------
__global__ void __launch_bounds__(NTHR, 1) traj_kernel(
    const float* z,
    const float* w1, const float* b1, const float* w2, const float* b2,
    const float* Wv, const float* bv, const float* Wo, const float* bo,
    const float* Wih0, const float* Whh0, const float* bih0, const float* bhh0,
    const float* Wih1, const float* Whh1, const float* bih1, const float* bhh1,
    const float* Wh, const float* bh,
    float* out, int T)
{
    __shared__ Smem sm;
    const int b = blockIdx.x;
    const int tid = threadIdx.x;
    const int ldo = T * LAT;

    // ===== P1: Wvo (64) | X1z (4) | bvo (32) | bhw1b1 (32) | zero X1 1..7 ===
    if (b < 64) {
        int mi = b >> 2, ni = b & 3;
        gemm_tile<1, false>(&sm, Wv + (size_t)mi * 64 * HID, 0, HID, HID,
                            Wo + ni * 256, HID, nullptr,
                            S_Wvo + (size_t)mi * 64 * HID + ni * 256, HID);
    } else if (b < 68) {
        int ni = b - 64;
        gemm_tile<1, false>(&sm, z, 0, LAT, LAT,
                            w1 + ni * 256, HID, b1 + ni * 256,
                            S_X1 + ni * 256, HID);
    } else if (b < 100) {
        vecmatK(&sm, bv, Wo, HID, HID, bo, S_bvo, (b - 68) * 32);
    } else if (b < 132) {
        vecmatK(&sm, bh, w1, HID, LAT, b1, S_bhw1b1, (b - 100) * 32);
    } else {
        float4* zx = (float4*)(S_X1 + GIN_STR);       // bufs 1..7
        for (int i = (b - 132) * NTHR + tid; i < 114688; i += 16 * NTHR)
            zx[i] = make_float4(0.f, 0.f, 0.f, 0.f);
    }
    gsync();

    // ===== P2: Wvoih0 = Wvo@Wih0 (192) + Whw1 = Wh@w1 (64) ==================
    for (int it = b; it < 256; it += NBLK) {
        if (it < 192) {
            int mi = it / 12, ni = it % 12;
            gemm_tile<1, false>(&sm, S_Wvo + (size_t)mi * 64 * HID, 0, HID, HID,
                                Wih0 + ni * 256, H3, nullptr,
                                S_Wvoih0 + (size_t)mi * 64 * H3 + ni * 256, H3);
        } else {
            int j = it - 192, mi = j >> 2, ni = j & 3;
            gemm_tile<1, false>(&sm, Wh + (size_t)mi * 64 * LAT, 0, LAT, LAT,
                                w1 + ni * 256, HID, nullptr,
                                S_Whw1 + (size_t)mi * 64 * HID + ni * 256, HID);
        }
    }
    gsync();

    // ===== P3: gin = relu(sum X1z)@w2+b2 (32 items) | bvoih0 (96) ===========
    if (b < 32)
        do_item<8, true>(&sm, b, 3, HID, S_X1, GIN_STR, HID,
                         w2, HID, b2, S_gin, GIN_STR, HID);
    else if (b < 128)
        vecmatK(&sm, S_bvo, Wih0, H3, HID, bih0, S_bvoih0, (b - 32) * 32);
    gsync();

    // ===== P4: gh0 = h0p@Whh0 (96, A = sum gin) | h1=h2=sum gin =============
    if (b < 96)
        do_item<8, false>(&sm, b, 3, HID, S_gin, GIN_STR, HID,
                          Whh0, H3, bhh0, S_gh0, GI_STR, H3);
    else {
        float4* h14 = (float4*)S_h1; float4* h24 = (float4*)S_h2;
        const float4* g4 = (const float4*)S_gin;
        for (int i = (b - 96) * NTHR + tid; i < BSZ * HID / 4; i += 52 * NTHR) {
            float4 v = g4[i];
            #pragma unroll
            for (int p = 1; p < 8; p++) v = add4(v, g4[p * (GIN_STR / 4) + i]);
            h14[i] = v; h24[i] = v;
        }
    }
    gsync();

    // ======================= time loop ======================================
    for (int t = 0; t < T; t++) {
        // S1: gi0 = act(sum gin)@Wvoih0+bvoih0 (96) | gh1' = h2@Whh1 (52)
        if (b < 96) {
            if (t == 0)
                do_item<8, false>(&sm, b, 3, HID, S_gin, GIN_STR, HID,
                                  S_Wvoih0, H3, S_bvoih0, S_gi, GI_STR, H3);
            else
                do_item<8, true>(&sm, b, 3, HID, S_gin, GIN_STR, HID,
                                 S_Wvoih0, H3, S_bvoih0, S_gi, GI_STR, H3);
        } else {
            do_item<1, false>(&sm, b - 96, 3, HID, S_h2, 0, HID,
                              Whh1, H3, bhh1, S_gh1, GI_STR, H3);
        }
        gsync();

        gru_stage(S_gi, S_gh0, S_h1);
        gsync();

        // S2: gi1 = h1@Wih1 (96) | gh1' rest (44) | gh0' (8)
        if (b < 96)
            do_item<1, false>(&sm, b, 3, HID, S_h1, 0, HID,
                              Wih1, H3, bih1, S_gi, GI_STR, H3);
        else if (b < 140)
            do_item<1, false>(&sm, 52 + (b - 96), 3, HID, S_h2, 0, HID,
                              Whh1, H3, bhh1, S_gh1, GI_STR, H3);
        else
            do_item<1, false>(&sm, b - 140, 3, HID, S_h1, 0, HID,
                              Whh0, H3, bhh0, S_gh0, GI_STR, H3);
        gsync();

        gru_stage(S_gi, S_gh1, S_h2);
        gsync();

        // S3: nz = h2@Wh (8) | X1 = h2@Whw1+bhw1b1 (32) | gh0' rest (88)
        if (b < 8)
            do_item<1, false>(&sm, b, 3, HID, S_h2, 0, HID,
                              Wh, LAT, bh, S_nz, NZ_STR, LAT);
        else if (b < 40)
            do_item<1, false>(&sm, b - 8, 3, HID, S_h2, 0, HID,
                              S_Whw1, HID, S_bhw1b1, S_X1, GIN_STR, HID);
        else if (b < 128)
            do_item<1, false>(&sm, 8 + (b - 40), 3, HID, S_h1, 0, HID,
                              Whh0, H3, bhh0, S_gh0, GI_STR, H3);
        gsync();

        // S4: gin = relu(sum X1)@w2+b2 (32) | out[:,t,:] = sum nz (8)
        if (b < 32)
            do_item<8, true>(&sm, b, 3, HID, S_X1, GIN_STR, HID,
                             w2, HID, b2, S_gin, GIN_STR, HID);
        else if (b < 40) {
            for (int e = (b - 32) * NTHR + tid; e < BSZ * LAT; e += 8 * NTHR) {
                float s = 0.f;
                #pragma unroll
                for (int p = 0; p < 8; p++) s += S_nz[p * NZ_STR + e];
                int m = e >> 8, c = e & 255;
                out[(size_t)m * ldo + (size_t)t * LAT + c] = s;
            }
        }
        gsync();
    }
}

// ---------------------------------------------------------------------------
extern "C" void kernel_launch(void* const* d_in, const int* in_sizes, int n_in,
                              void* d_out, int out_size)
{
    (void)in_sizes; (void)n_in;
    const float* z    = (const float*)d_in[0];
    // d_in[1] = max_len (device int32); T derived from out_size.
    const float* w1   = (const float*)d_in[2];
    const float* b1   = (const float*)d_in[3];
    const float* w2   = (const float*)d_in[4];
    const float* b2   = (const float*)d_in[5];
    // d_in[6..9] = Wq, bq, Wk, bk — dead (softmax over a single key == 1).
    const float* Wv   = (const float*)d_in[10];
    const float* bv   = (const float*)d_in[11];
    const float* Wo   = (const float*)d_in[12];
    const float* bo   = (const float*)d_in[13];
    const float* Wih0 = (const float*)d_in[14];
    const float* Whh0 = (const float*)d_in[15];
    const float* bih0 = (const float*)d_in[16];
    const float* bhh0 = (const float*)d_in[17];
    const float* Wih1 = (const float*)d_in[18];
    const float* Whh1 = (const float*)d_in[19];
    const float* bih1 = (const float*)d_in[20];
    const float* bhh1 = (const float*)d_in[21];
    const float* Wh   = (const float*)d_in[22];
    const float* bh   = (const float*)d_in[23];
    float* out = (float*)d_out;

    const int T = out_size / (BSZ * LAT);   // 128

    traj_kernel<<<NBLK, NTHR>>>(
        z, w1, b1, w2, b2, Wv, bv, Wo, bo,
        Wih0, Whh0, bih0, bhh0, Wih1, Whh1, bih1, bhh1,
        Wh, bh, out, T);
}